// round 2
// baseline (speedup 1.0000x reference)
#include <cuda_runtime.h>
#include <cuda_bf16.h>

// Problem constants
#define Bb   2
#define Nn   16384
#define Ss   4096
#define Kk   32
#define Fin  16
#define FD   19      // Fin + 3
#define H1D  64
#define H2D  64
#define H3D  128

// -------- scratch (device globals; no allocation allowed) --------
__device__ float g_centers[Bb * Ss * 3];
__device__ int   g_nbr[Bb * Ss * Kk];
__device__ int   g_cnt[Bb * Ss];

// ======================= FPS =======================
// One CTA per cloud. 1024 threads, 16 points per thread held in registers.
// Selection: idx[0]=0, then 4095 serial argmax steps over running dmin.
#define FPS_T 1024
#define NPT   (Nn / FPS_T)   // 16

__global__ __launch_bounds__(FPS_T, 1) void fps_kernel(const float* __restrict__ pos) {
    const int b = blockIdx.x;
    const int t = threadIdx.x;
    const float* __restrict__ p = pos + (size_t)b * Nn * 3;

    float px[NPT], py[NPT], pz[NPT], dm[NPT];
#pragma unroll
    for (int i = 0; i < NPT; i++) {
        int n = t + i * FPS_T;
        px[i] = p[n * 3 + 0];
        py[i] = p[n * 3 + 1];
        pz[i] = p[n * 3 + 2];
        dm[i] = 1e10f;
    }

    __shared__ float s_l[3];
    __shared__ float s_wv[32];
    __shared__ int   s_wi[32];

    if (t == 0) {
        s_l[0] = p[0]; s_l[1] = p[1]; s_l[2] = p[2];
        size_t o = (size_t)b * Ss * 3;
        g_centers[o + 0] = p[0];
        g_centers[o + 1] = p[1];
        g_centers[o + 2] = p[2];
    }
    __syncthreads();

    for (int s = 1; s < Ss; s++) {
        float lx = s_l[0], ly = s_l[1], lz = s_l[2];
        float bv = -1.0f; int bl = 0;
#pragma unroll
        for (int i = 0; i < NPT; i++) {
            float dx = px[i] - lx, dy = py[i] - ly, dz = pz[i] - lz;
            float d = fmaf(dz, dz, fmaf(dy, dy, dx * dx));
            float m = fminf(dm[i], d);
            dm[i] = m;
            if (m > bv) { bv = m; bl = i; }   // within-thread: first (smallest) index wins
        }
        int bi = t + bl * FPS_T;
        // warp argmax (value desc, index asc on ties)
#pragma unroll
        for (int off = 16; off > 0; off >>= 1) {
            float ov = __shfl_down_sync(0xffffffffu, bv, off);
            int   oi = __shfl_down_sync(0xffffffffu, bi, off);
            if (ov > bv || (ov == bv && oi < bi)) { bv = ov; bi = oi; }
        }
        if ((t & 31) == 0) { s_wv[t >> 5] = bv; s_wi[t >> 5] = bi; }
        __syncthreads();
        if (t < 32) {
            bv = s_wv[t]; bi = s_wi[t];
#pragma unroll
            for (int off = 16; off > 0; off >>= 1) {
                float ov = __shfl_down_sync(0xffffffffu, bv, off);
                int   oi = __shfl_down_sync(0xffffffffu, bi, off);
                if (ov > bv || (ov == bv && oi < bi)) { bv = ov; bi = oi; }
            }
            if (t == 0) {
                float cx = p[bi * 3 + 0], cy = p[bi * 3 + 1], cz = p[bi * 3 + 2];
                s_l[0] = cx; s_l[1] = cy; s_l[2] = cz;
                size_t o = ((size_t)b * Ss + s) * 3;
                g_centers[o + 0] = cx; g_centers[o + 1] = cy; g_centers[o + 2] = cz;
            }
        }
        __syncthreads();
    }
}

// ======================= Ball query =======================
// Warp per center: scan points in index order, ballot-compact first K hits.
__global__ __launch_bounds__(256) void bq_kernel(const float* __restrict__ pos) {
    int w = (blockIdx.x * blockDim.x + threadIdx.x) >> 5;   // center id 0..B*S-1
    int lane = threadIdx.x & 31;
    if (w >= Bb * Ss) return;
    int b = w / Ss;
    int s = w - b * Ss;

    float cx = g_centers[w * 3 + 0];
    float cy = g_centers[w * 3 + 1];
    float cz = g_centers[w * 3 + 2];
    const float* __restrict__ p = pos + (size_t)b * Nn * 3;

    // remove_self_loops: global src == global dst  <=>  n == b*S + s - b*N
    int selfn = b * Ss + s - b * Nn;   // for b=1 this is negative -> never matches
    const float rr = 0.1f * 0.1f;

    int cnt = 0;
    for (int n0 = 0; n0 < Nn; n0 += 32) {
        int n = n0 + lane;
        float x = p[n * 3 + 0], y = p[n * 3 + 1], z = p[n * 3 + 2];
        float dx = x - cx, dy = y - cy, dz = z - cz;
        float d = fmaf(dz, dz, fmaf(dy, dy, dx * dx));
        bool ok = (d <= rr) && (n != selfn);
        unsigned m = __ballot_sync(0xffffffffu, ok);
        int rank = __popc(m & ((1u << lane) - 1u));
        if (ok && (cnt + rank) < Kk) g_nbr[w * Kk + cnt + rank] = n;
        cnt += __popc(m);
        if (cnt >= Kk) { cnt = Kk; break; }
    }
    if (lane == 0) g_cnt[w] = cnt < Kk ? cnt : Kk;
}

// ======================= MLP + max aggregation =======================
// Warp per center; 4 warps/block. W1,W2,biases in static smem; W3 via L1.
// Neighbors processed 4 at a time to amortize weight loads.
#define MWPB 4       // warps per block
#define NU   4       // neighbor unroll

__global__ __launch_bounds__(128) void mlp_kernel(
    const float* __restrict__ x, const float* __restrict__ pos,
    const float* __restrict__ W1, const float* __restrict__ b1,
    const float* __restrict__ W2, const float* __restrict__ b2,
    const float* __restrict__ W3, const float* __restrict__ b3,
    float* __restrict__ out)
{
    __shared__ float sW1[FD * H1D];      // 1216
    __shared__ float sb1[H1D];
    __shared__ float sW2[H1D * H2D];     // 4096
    __shared__ float sb2[H2D];
    __shared__ float sb3[H3D];
    __shared__ float sF [MWPB * 36 * FD];      // 2736
    __shared__ float sH1[MWPB * NU * H1D];     // 1024
    __shared__ float sH2[MWPB * NU * H2D];     // 1024

    const int tid = threadIdx.x;
    for (int i = tid; i < FD * H1D; i += 128) sW1[i] = W1[i];
    for (int i = tid; i < H1D * H2D; i += 128) sW2[i] = W2[i];
    if (tid < H1D) { sb1[tid] = b1[tid]; sb2[tid] = b2[tid]; }
    if (tid < H3D) sb3[tid] = b3[tid];
    __syncthreads();

    const int w = tid >> 5, lane = tid & 31;
    const int cs = blockIdx.x * MWPB + w;          // center id
    const int b = cs / Ss;
    const int cnt = g_cnt[cs];
    const float cx = g_centers[cs * 3 + 0];
    const float cy = g_centers[cs * 3 + 1];
    const float cz = g_centers[cs * 3 + 2];

    float* F = sF + w * 36 * FD;

    // gather neighbor features: [x(16), pos - center(3)]
    if (lane < cnt) {
        int n = g_nbr[cs * Kk + lane];
        int src = b * Nn + n;
        const float4* xr = reinterpret_cast<const float4*>(x + (size_t)src * Fin);
        float* f = F + lane * FD;
#pragma unroll
        for (int q = 0; q < 4; q++) {
            float4 v = xr[q];
            f[4 * q + 0] = v.x; f[4 * q + 1] = v.y; f[4 * q + 2] = v.z; f[4 * q + 3] = v.w;
        }
        f[16] = pos[src * 3 + 0] - cx;
        f[17] = pos[src * 3 + 1] - cy;
        f[18] = pos[src * 3 + 2] - cz;
    }
    if (lane == 0) {
        // add_self_loops edge: src is FLAT point index (b*S + s) == cs
        int src = cs;
        const float4* xr = reinterpret_cast<const float4*>(x + (size_t)src * Fin);
        float* f = F + cnt * FD;
#pragma unroll
        for (int q = 0; q < 4; q++) {
            float4 v = xr[q];
            f[4 * q + 0] = v.x; f[4 * q + 1] = v.y; f[4 * q + 2] = v.z; f[4 * q + 3] = v.w;
        }
        f[16] = pos[src * 3 + 0] - cx;
        f[17] = pos[src * 3 + 1] - cy;
        f[18] = pos[src * 3 + 2] - cz;
    }
    __syncwarp();

    const int nv = cnt + 1;
    float mx0 = -3.0e38f, mx1 = -3.0e38f, mx2 = -3.0e38f, mx3 = -3.0e38f;
    float* Hb1 = sH1 + w * NU * H1D;
    float* Hb2 = sH2 + w * NU * H2D;

    for (int j0 = 0; j0 < nv; j0 += NU) {
        // ---- layer 1: [NU,19] @ [19,64], relu ----
        float a0[NU], a1[NU];
#pragma unroll
        for (int u = 0; u < NU; u++) { a0[u] = sb1[lane]; a1[u] = sb1[lane + 32]; }
#pragma unroll
        for (int i = 0; i < FD; i++) {
            float w0 = sW1[i * H1D + lane];
            float w1 = sW1[i * H1D + 32 + lane];
#pragma unroll
            for (int u = 0; u < NU; u++) {
                float f = F[(j0 + u) * FD + i];
                a0[u] = fmaf(f, w0, a0[u]);
                a1[u] = fmaf(f, w1, a1[u]);
            }
        }
#pragma unroll
        for (int u = 0; u < NU; u++) {
            Hb1[u * H1D + lane]      = fmaxf(a0[u], 0.0f);
            Hb1[u * H1D + 32 + lane] = fmaxf(a1[u], 0.0f);
        }
        __syncwarp();

        // ---- layer 2: [NU,64] @ [64,64], relu ----
#pragma unroll
        for (int u = 0; u < NU; u++) { a0[u] = sb2[lane]; a1[u] = sb2[lane + 32]; }
#pragma unroll 8
        for (int i = 0; i < H1D; i++) {
            float w0 = sW2[i * H2D + lane];
            float w1 = sW2[i * H2D + 32 + lane];
#pragma unroll
            for (int u = 0; u < NU; u++) {
                float v = Hb1[u * H1D + i];
                a0[u] = fmaf(v, w0, a0[u]);
                a1[u] = fmaf(v, w1, a1[u]);
            }
        }
#pragma unroll
        for (int u = 0; u < NU; u++) {
            Hb2[u * H2D + lane]      = fmaxf(a0[u], 0.0f);
            Hb2[u * H2D + 32 + lane] = fmaxf(a1[u], 0.0f);
        }
        __syncwarp();

        // ---- layer 3: [NU,64] @ [64,128] (no relu), running max ----
        float c0[NU], c1[NU], c2[NU], c3[NU];
#pragma unroll
        for (int u = 0; u < NU; u++) {
            c0[u] = sb3[lane];      c1[u] = sb3[lane + 32];
            c2[u] = sb3[lane + 64]; c3[u] = sb3[lane + 96];
        }
#pragma unroll 4
        for (int i = 0; i < H2D; i++) {
            float w0 = __ldg(W3 + i * H3D + lane);
            float w1 = __ldg(W3 + i * H3D + 32 + lane);
            float w2 = __ldg(W3 + i * H3D + 64 + lane);
            float w3 = __ldg(W3 + i * H3D + 96 + lane);
#pragma unroll
            for (int u = 0; u < NU; u++) {
                float v = Hb2[u * H2D + i];
                c0[u] = fmaf(v, w0, c0[u]);
                c1[u] = fmaf(v, w1, c1[u]);
                c2[u] = fmaf(v, w2, c2[u]);
                c3[u] = fmaf(v, w3, c3[u]);
            }
        }
#pragma unroll
        for (int u = 0; u < NU; u++) {
            if (j0 + u < nv) {
                mx0 = fmaxf(mx0, c0[u]);
                mx1 = fmaxf(mx1, c1[u]);
                mx2 = fmaxf(mx2, c2[u]);
                mx3 = fmaxf(mx3, c3[u]);
            }
        }
        __syncwarp();
    }

    size_t o = (size_t)cs * H3D;
    out[o + lane]      = mx0;
    out[o + 32 + lane] = mx1;
    out[o + 64 + lane] = mx2;
    out[o + 96 + lane] = mx3;
}

// ======================= tail: centers + batch sections =======================
__global__ void tail_kernel(float* __restrict__ out, int out_size) {
    int i = blockIdx.x * blockDim.x + threadIdx.x;
    const int NX = Bb * Ss * H3D;          // 1048576
    const int NC = Bb * Ss * 3;            // 24576
    const int NB = Bb * Ss;                // 8192
    if (out_size >= NX + NC) {
        if (i < NC) out[NX + i] = g_centers[i];
    }
    if (out_size >= NX + NC + NB) {
        if (i < NB) out[NX + NC + i] = (float)(i / Ss);
    }
}

// ======================= launch =======================
extern "C" void kernel_launch(void* const* d_in, const int* in_sizes, int n_in,
                              void* d_out, int out_size) {
    const float* x   = (const float*)d_in[0];
    const float* pos = (const float*)d_in[1];
    // d_in[2] = batch (unused; implied by layout)
    const float* W1  = (const float*)d_in[3];
    const float* b1  = (const float*)d_in[4];
    const float* W2  = (const float*)d_in[5];
    const float* b2  = (const float*)d_in[6];
    const float* W3  = (const float*)d_in[7];
    const float* b3  = (const float*)d_in[8];
    float* out = (float*)d_out;

    fps_kernel<<<Bb, FPS_T>>>(pos);
    bq_kernel<<<(Bb * Ss * 32) / 256, 256>>>(pos);
    mlp_kernel<<<(Bb * Ss) / MWPB, 128>>>(x, pos, W1, b1, W2, b2, W3, b3, out);
    tail_kernel<<<(Bb * Ss * 3 + 255) / 256, 256>>>(out, out_size);
}

// round 3
// speedup vs baseline: 2.2544x; 2.2544x over previous
#include <cuda_runtime.h>
#include <cuda_bf16.h>
#include <cooperative_groups.h>

namespace cg = cooperative_groups;

// Problem constants
#define Bb   2
#define Nn   16384
#define Ss   4096
#define Kk   32
#define Fin  16
#define FD   19      // Fin + 3
#define H1D  64
#define H2D  64
#define H3D  128

// -------- scratch (device globals; no allocation allowed) --------
__device__ float g_centers[Bb * Ss * 3];
__device__ int   g_nbr[Bb * Ss * Kk];
__device__ int   g_cnt[Bb * Ss];

// ======================= FPS (clustered) =======================
#define FPS_CTAS 8                 // CTAs per cloud (one cluster)
#define FPS_T    256               // threads per CTA
#define PPC      (Nn / FPS_CTAS)   // 2048 points per CTA
#define PPT      (PPC / FPS_T)     // 8 points per thread
#define PKT      (PPT / 2)         // 4 f32x2 packets per coord

typedef unsigned long long u64;

__device__ __forceinline__ u64 pk2(float lo, float hi) {
    u64 r; asm("mov.b64 %0, {%1, %2};" : "=l"(r) : "f"(lo), "f"(hi)); return r;
}
__device__ __forceinline__ void upk2(u64 v, float& lo, float& hi) {
    asm("mov.b64 {%0, %1}, %2;" : "=f"(lo), "=f"(hi) : "l"(v));
}
__device__ __forceinline__ u64 add2(u64 a, u64 b) {
    u64 r; asm("add.rn.f32x2 %0, %1, %2;" : "=l"(r) : "l"(a), "l"(b)); return r;
}
__device__ __forceinline__ u64 mul2(u64 a, u64 b) {
    u64 r; asm("mul.rn.f32x2 %0, %1, %2;" : "=l"(r) : "l"(a), "l"(b)); return r;
}
__device__ __forceinline__ u64 fma2(u64 a, u64 b, u64 c) {
    u64 r; asm("fma.rn.f32x2 %0, %1, %2, %3;" : "=l"(r) : "l"(a), "l"(b), "l"(c)); return r;
}

__global__ __launch_bounds__(FPS_T, 1) __cluster_dims__(FPS_CTAS, 1, 1)
void fps_kernel(const float* __restrict__ pos) {
    cg::cluster_group cl = cg::this_cluster();
    const int rank = (int)cl.block_rank();
    const int b    = blockIdx.x / FPS_CTAS;
    const int t    = threadIdx.x;
    const int lane = t & 31;
    const int warp = t >> 5;
    const float* __restrict__ p = pos + (size_t)b * Nn * 3;
    const int base = rank * PPC;

    __shared__ float    s_x[PPC], s_y[PPC], s_z[PPC];
    __shared__ unsigned s_wv[8];
    __shared__ unsigned s_wi[8];
    __shared__ unsigned s_rec[2][FPS_CTAS][8];   // [buf][src rank][vb, idx, xb, yb, zb]

    // load this CTA's shard into registers (packed) and smem (for coord publish)
    float px[PPT], py[PPT], pz[PPT], dm[PPT];
#pragma unroll
    for (int i = 0; i < PPT; i++) {
        int li = i * FPS_T + t;
        int n = base + li;
        float x = p[n * 3 + 0], y = p[n * 3 + 1], z = p[n * 3 + 2];
        px[i] = x; py[i] = y; pz[i] = z;
        s_x[li] = x; s_y[li] = y; s_z[li] = z;
        dm[i] = 1e10f;
    }
    u64 pxp[PKT], pyp[PKT], pzp[PKT];
#pragma unroll
    for (int j = 0; j < PKT; j++) {
        pxp[j] = pk2(px[2 * j], px[2 * j + 1]);
        pyp[j] = pk2(py[2 * j], py[2 * j + 1]);
        pzp[j] = pk2(pz[2 * j], pz[2 * j + 1]);
    }

    // first center = point 0
    float lx = p[0], ly = p[1], lz = p[2];
    if (rank == 0 && t == 0) {
        size_t o = (size_t)b * Ss * 3;
        g_centers[o + 0] = lx; g_centers[o + 1] = ly; g_centers[o + 2] = lz;
    }
    int buf = 0;

    for (int s = 1; s < Ss; s++) {
        // ---- distance update + running max (packed f32x2, bit-identical per lane) ----
        u64 nx2 = pk2(-lx, -lx), ny2 = pk2(-ly, -ly), nz2 = pk2(-lz, -lz);
        float bv0 = -1.0f, bv1 = -1.0f;
#pragma unroll
        for (int j = 0; j < PKT; j++) {
            u64 dx = add2(pxp[j], nx2);
            u64 dy = add2(pyp[j], ny2);
            u64 dz = add2(pzp[j], nz2);
            u64 d  = fma2(dz, dz, fma2(dy, dy, mul2(dx, dx)));
            float d0, d1; upk2(d, d0, d1);
            float m0 = fminf(dm[2 * j], d0);
            float m1 = fminf(dm[2 * j + 1], d1);
            dm[2 * j] = m0; dm[2 * j + 1] = m1;
            bv0 = fmaxf(bv0, m0);
            bv1 = fmaxf(bv1, m1);
        }
        float bv = fmaxf(bv0, bv1);

        // recover smallest local slot achieving bv (slots ascend in global index)
        int bl = 0;
#pragma unroll
        for (int i = PPT - 1; i >= 0; i--) if (dm[i] == bv) bl = i;
        unsigned gi = (unsigned)(base + bl * FPS_T + t);

        // ---- warp argmax (value desc, index asc) via redux ----
        unsigned vb   = __float_as_uint(bv);                  // >=0 -> monotone bits
        unsigned wmax = __reduce_max_sync(0xffffffffu, vb);
        unsigned cand = (vb == wmax) ? gi : 0xffffffffu;
        unsigned widx = __reduce_min_sync(0xffffffffu, cand);
        if (lane == 0) { s_wv[warp] = wmax; s_wi[warp] = widx; }
        __syncthreads();

        // ---- block argmax + publish to all CTAs (warp 0) ----
        if (warp == 0) {
            unsigned v2 = (lane < 8) ? s_wv[lane] : 0u;
            unsigned i2 = (lane < 8) ? s_wi[lane] : 0xffffffffu;
            unsigned bmax = __reduce_max_sync(0xffffffffu, v2);
            unsigned c2   = (v2 == bmax) ? i2 : 0xffffffffu;
            unsigned bidx = __reduce_min_sync(0xffffffffu, c2);
            if (lane == 0) {
                int li = (int)bidx - base;
                unsigned cx = __float_as_uint(s_x[li]);
                unsigned cy = __float_as_uint(s_y[li]);
                unsigned cz = __float_as_uint(s_z[li]);
#pragma unroll
                for (int r = 0; r < FPS_CTAS; r++) {
                    unsigned* rec = cl.map_shared_rank(&s_rec[buf][rank][0], r);
                    rec[0] = bmax; rec[1] = bidx;
                    rec[2] = cx;   rec[3] = cy;   rec[4] = cz;
                }
            }
        }
        cl.sync();

        // ---- every thread reduces the 8 records -> cluster winner ----
        unsigned gvb = 0u, gidx = 0xffffffffu, gx = 0, gy = 0, gz = 0;
#pragma unroll
        for (int r = 0; r < FPS_CTAS; r++) {
            const unsigned* rec = &s_rec[buf][r][0];
            unsigned v = rec[0], ix = rec[1];
            if (v > gvb || (v == gvb && ix < gidx)) {
                gvb = v; gidx = ix; gx = rec[2]; gy = rec[3]; gz = rec[4];
            }
        }
        lx = __uint_as_float(gx); ly = __uint_as_float(gy); lz = __uint_as_float(gz);
        if (rank == 0 && t == 0) {
            size_t o = ((size_t)b * Ss + s) * 3;
            g_centers[o + 0] = lx; g_centers[o + 1] = ly; g_centers[o + 2] = lz;
        }
        buf ^= 1;
    }
}

// ======================= Ball query =======================
__global__ __launch_bounds__(256) void bq_kernel(const float* __restrict__ pos) {
    int w = (blockIdx.x * blockDim.x + threadIdx.x) >> 5;   // center id 0..B*S-1
    int lane = threadIdx.x & 31;
    if (w >= Bb * Ss) return;
    int b = w / Ss;
    int s = w - b * Ss;

    float cx = g_centers[w * 3 + 0];
    float cy = g_centers[w * 3 + 1];
    float cz = g_centers[w * 3 + 2];
    const float* __restrict__ p = pos + (size_t)b * Nn * 3;

    int selfn = b * Ss + s - b * Nn;   // remove_self_loops (only hits for b=0)
    const float rr = 0.1f * 0.1f;

    int cnt = 0;
    for (int n0 = 0; n0 < Nn; n0 += 32) {
        int n = n0 + lane;
        float x = p[n * 3 + 0], y = p[n * 3 + 1], z = p[n * 3 + 2];
        float dx = x - cx, dy = y - cy, dz = z - cz;
        float d = fmaf(dz, dz, fmaf(dy, dy, dx * dx));
        bool ok = (d <= rr) && (n != selfn);
        unsigned m = __ballot_sync(0xffffffffu, ok);
        int rank = __popc(m & ((1u << lane) - 1u));
        if (ok && (cnt + rank) < Kk) g_nbr[w * Kk + cnt + rank] = n;
        cnt += __popc(m);
        if (cnt >= Kk) { cnt = Kk; break; }
    }
    if (lane == 0) g_cnt[w] = cnt < Kk ? cnt : Kk;
}

// ======================= MLP + max aggregation =======================
#define MWPB 4       // warps per block
#define NU   4       // neighbor unroll

__global__ __launch_bounds__(128) void mlp_kernel(
    const float* __restrict__ x, const float* __restrict__ pos,
    const float* __restrict__ W1, const float* __restrict__ b1,
    const float* __restrict__ W2, const float* __restrict__ b2,
    const float* __restrict__ W3, const float* __restrict__ b3,
    float* __restrict__ out)
{
    __shared__ float sW1[FD * H1D];
    __shared__ float sb1[H1D];
    __shared__ float sW2[H1D * H2D];
    __shared__ float sb2[H2D];
    __shared__ float sb3[H3D];
    __shared__ float sF [MWPB * 36 * FD];
    __shared__ float sH1[MWPB * NU * H1D];
    __shared__ float sH2[MWPB * NU * H2D];

    const int tid = threadIdx.x;
    for (int i = tid; i < FD * H1D; i += 128) sW1[i] = W1[i];
    for (int i = tid; i < H1D * H2D; i += 128) sW2[i] = W2[i];
    if (tid < H1D) { sb1[tid] = b1[tid]; sb2[tid] = b2[tid]; }
    if (tid < H3D) sb3[tid] = b3[tid];
    __syncthreads();

    const int w = tid >> 5, lane = tid & 31;
    const int cs = blockIdx.x * MWPB + w;
    const int b = cs / Ss;
    const int cnt = g_cnt[cs];
    const float cx = g_centers[cs * 3 + 0];
    const float cy = g_centers[cs * 3 + 1];
    const float cz = g_centers[cs * 3 + 2];

    float* F = sF + w * 36 * FD;

    if (lane < cnt) {
        int n = g_nbr[cs * Kk + lane];
        int src = b * Nn + n;
        const float4* xr = reinterpret_cast<const float4*>(x + (size_t)src * Fin);
        float* f = F + lane * FD;
#pragma unroll
        for (int q = 0; q < 4; q++) {
            float4 v = xr[q];
            f[4 * q + 0] = v.x; f[4 * q + 1] = v.y; f[4 * q + 2] = v.z; f[4 * q + 3] = v.w;
        }
        f[16] = pos[src * 3 + 0] - cx;
        f[17] = pos[src * 3 + 1] - cy;
        f[18] = pos[src * 3 + 2] - cz;
    }
    if (lane == 0) {
        int src = cs;  // add_self_loops: src is the FLAT dst index
        const float4* xr = reinterpret_cast<const float4*>(x + (size_t)src * Fin);
        float* f = F + cnt * FD;
#pragma unroll
        for (int q = 0; q < 4; q++) {
            float4 v = xr[q];
            f[4 * q + 0] = v.x; f[4 * q + 1] = v.y; f[4 * q + 2] = v.z; f[4 * q + 3] = v.w;
        }
        f[16] = pos[src * 3 + 0] - cx;
        f[17] = pos[src * 3 + 1] - cy;
        f[18] = pos[src * 3 + 2] - cz;
    }
    __syncwarp();

    const int nv = cnt + 1;
    float mx0 = -3.0e38f, mx1 = -3.0e38f, mx2 = -3.0e38f, mx3 = -3.0e38f;
    float* Hb1 = sH1 + w * NU * H1D;
    float* Hb2 = sH2 + w * NU * H2D;

    for (int j0 = 0; j0 < nv; j0 += NU) {
        float a0[NU], a1[NU];
#pragma unroll
        for (int u = 0; u < NU; u++) { a0[u] = sb1[lane]; a1[u] = sb1[lane + 32]; }
#pragma unroll
        for (int i = 0; i < FD; i++) {
            float w0 = sW1[i * H1D + lane];
            float w1 = sW1[i * H1D + 32 + lane];
#pragma unroll
            for (int u = 0; u < NU; u++) {
                float f = F[(j0 + u) * FD + i];
                a0[u] = fmaf(f, w0, a0[u]);
                a1[u] = fmaf(f, w1, a1[u]);
            }
        }
#pragma unroll
        for (int u = 0; u < NU; u++) {
            Hb1[u * H1D + lane]      = fmaxf(a0[u], 0.0f);
            Hb1[u * H1D + 32 + lane] = fmaxf(a1[u], 0.0f);
        }
        __syncwarp();

#pragma unroll
        for (int u = 0; u < NU; u++) { a0[u] = sb2[lane]; a1[u] = sb2[lane + 32]; }
#pragma unroll 8
        for (int i = 0; i < H1D; i++) {
            float w0 = sW2[i * H2D + lane];
            float w1 = sW2[i * H2D + 32 + lane];
#pragma unroll
            for (int u = 0; u < NU; u++) {
                float v = Hb1[u * H1D + i];
                a0[u] = fmaf(v, w0, a0[u]);
                a1[u] = fmaf(v, w1, a1[u]);
            }
        }
#pragma unroll
        for (int u = 0; u < NU; u++) {
            Hb2[u * H2D + lane]      = fmaxf(a0[u], 0.0f);
            Hb2[u * H2D + 32 + lane] = fmaxf(a1[u], 0.0f);
        }
        __syncwarp();

        float c0[NU], c1[NU], c2[NU], c3[NU];
#pragma unroll
        for (int u = 0; u < NU; u++) {
            c0[u] = sb3[lane];      c1[u] = sb3[lane + 32];
            c2[u] = sb3[lane + 64]; c3[u] = sb3[lane + 96];
        }
#pragma unroll 4
        for (int i = 0; i < H2D; i++) {
            float w0 = __ldg(W3 + i * H3D + lane);
            float w1 = __ldg(W3 + i * H3D + 32 + lane);
            float w2 = __ldg(W3 + i * H3D + 64 + lane);
            float w3 = __ldg(W3 + i * H3D + 96 + lane);
#pragma unroll
            for (int u = 0; u < NU; u++) {
                float v = Hb2[u * H2D + i];
                c0[u] = fmaf(v, w0, c0[u]);
                c1[u] = fmaf(v, w1, c1[u]);
                c2[u] = fmaf(v, w2, c2[u]);
                c3[u] = fmaf(v, w3, c3[u]);
            }
        }
#pragma unroll
        for (int u = 0; u < NU; u++) {
            if (j0 + u < nv) {
                mx0 = fmaxf(mx0, c0[u]);
                mx1 = fmaxf(mx1, c1[u]);
                mx2 = fmaxf(mx2, c2[u]);
                mx3 = fmaxf(mx3, c3[u]);
            }
        }
        __syncwarp();
    }

    size_t o = (size_t)cs * H3D;
    out[o + lane]      = mx0;
    out[o + 32 + lane] = mx1;
    out[o + 64 + lane] = mx2;
    out[o + 96 + lane] = mx3;
}

// ======================= tail: centers + batch sections =======================
__global__ void tail_kernel(float* __restrict__ out, int out_size) {
    int i = blockIdx.x * blockDim.x + threadIdx.x;
    const int NX = Bb * Ss * H3D;
    const int NC = Bb * Ss * 3;
    const int NB = Bb * Ss;
    if (out_size >= NX + NC) {
        if (i < NC) out[NX + i] = g_centers[i];
    }
    if (out_size >= NX + NC + NB) {
        if (i < NB) out[NX + NC + i] = (float)(i / Ss);
    }
}

// ======================= launch =======================
extern "C" void kernel_launch(void* const* d_in, const int* in_sizes, int n_in,
                              void* d_out, int out_size) {
    const float* x   = (const float*)d_in[0];
    const float* pos = (const float*)d_in[1];
    const float* W1  = (const float*)d_in[3];
    const float* b1  = (const float*)d_in[4];
    const float* W2  = (const float*)d_in[5];
    const float* b2  = (const float*)d_in[6];
    const float* W3  = (const float*)d_in[7];
    const float* b3  = (const float*)d_in[8];
    float* out = (float*)d_out;

    fps_kernel<<<Bb * FPS_CTAS, FPS_T>>>(pos);
    bq_kernel<<<(Bb * Ss * 32) / 256, 256>>>(pos);
    mlp_kernel<<<(Bb * Ss) / MWPB, 128>>>(x, pos, W1, b1, W2, b2, W3, b3, out);
    tail_kernel<<<(Bb * Ss * 3 + 255) / 256, 256>>>(out, out_size);
}